// round 1
// baseline (speedup 1.0000x reference)
#include <cuda_runtime.h>
#include <cuda_bf16.h>
#include <math.h>

// Problem constants
#define BATCH   4
#define SEQ     4096
#define EMBED   1024
#define HEADS   16
#define HDIM    64
#define MROWS   (BATCH * SEQ)          // 16384
#define QKV_N   (3 * EMBED)            // 3072

// Scratch (static device globals — the sanctioned alloc-free workaround)
__device__ float g_qkv[(size_t)MROWS * QKV_N];   // 192 MB: [16384, 3072]
__device__ float g_y[(size_t)MROWS * EMBED];     //  64 MB: attention output pre-projection
__device__ float g_kv[BATCH * HEADS * HDIM * HDIM]; // [64][64][64] : kv[bh][dk][dv]
__device__ float g_ksum[BATCH * HEADS * HDIM];      // [64][64]

// ---------------------------------------------------------------------------
// Zero kv/ksum accumulators (needed every replay; atomics accumulate into them)
// ---------------------------------------------------------------------------
__global__ void zero_acc_kernel() {
    int i = blockIdx.x * 256 + threadIdx.x;
    if (i < BATCH * HEADS * HDIM * HDIM) g_kv[i] = 0.0f;
    if (i < BATCH * HEADS * HDIM)        g_ksum[i] = 0.0f;
}

// ---------------------------------------------------------------------------
// Classic 128x128x8 SGEMM, 256 threads, 8x8 per thread (4x4 quadrants).
// MODE 0: C = A @ W, apply elu(x)+1 to columns < 2*EMBED (q and k parts)
// MODE 1: C = A @ W + bias
// All dims are exact multiples of the tile sizes -> no bounds checks.
// ---------------------------------------------------------------------------
template <int MODE>
__device__ __forceinline__ void gemm_body(
    const float* __restrict__ A,    // [M, K] row-major
    const float* __restrict__ W,    // [K, N] row-major
    float* __restrict__ C,          // [M, N]
    const float* __restrict__ bias, // [N] (MODE 1 only)
    int N, int K)
{
    __shared__ float As[8][128];
    __shared__ float Bs[8][128];

    const int tid = threadIdx.x;          // 0..255
    const int bx = blockIdx.x;            // N tile
    const int by = blockIdx.y;            // M tile
    const int tx = tid & 15;              // 0..15
    const int ty = tid >> 4;              // 0..15

    // A loader: row = tid/2 (0..127), 4 cols at (tid%2)*4
    const int a_row = tid >> 1;
    const int a_col = (tid & 1) * 4;
    const float* a_ptr = A + (size_t)(by * 128 + a_row) * K + a_col;

    // B loader: row = tid/32 (0..7), 4 cols at (tid%32)*4
    const int b_row = tid >> 5;
    const int b_col = (tid & 31) * 4;
    const float* b_ptr = W + (size_t)b_row * N + bx * 128 + b_col;

    float acc[8][8];
#pragma unroll
    for (int i = 0; i < 8; i++)
#pragma unroll
        for (int j = 0; j < 8; j++) acc[i][j] = 0.0f;

    for (int k0 = 0; k0 < K; k0 += 8) {
        // load A tile (transposed into As[k][m])
        float4 av = *(const float4*)(a_ptr);
        As[a_col + 0][a_row] = av.x;
        As[a_col + 1][a_row] = av.y;
        As[a_col + 2][a_row] = av.z;
        As[a_col + 3][a_row] = av.w;
        // load B tile
        float4 bv = *(const float4*)(b_ptr);
        *(float4*)&Bs[b_row][b_col] = bv;
        __syncthreads();

#pragma unroll
        for (int kk = 0; kk < 8; kk++) {
            float4 a0 = *(const float4*)&As[kk][ty * 4];
            float4 a1 = *(const float4*)&As[kk][64 + ty * 4];
            float4 b0 = *(const float4*)&Bs[kk][tx * 4];
            float4 b1 = *(const float4*)&Bs[kk][64 + tx * 4];
            float a[8] = {a0.x, a0.y, a0.z, a0.w, a1.x, a1.y, a1.z, a1.w};
            float b[8] = {b0.x, b0.y, b0.z, b0.w, b1.x, b1.y, b1.z, b1.w};
#pragma unroll
            for (int i = 0; i < 8; i++)
#pragma unroll
                for (int j = 0; j < 8; j++) acc[i][j] += a[i] * b[j];
        }
        __syncthreads();
        a_ptr += 8;
        b_ptr += (size_t)8 * N;
    }

    // epilogue
    const int row0 = by * 128 + ty * 4;
    const int col0 = bx * 128 + tx * 4;
#pragma unroll
    for (int ii = 0; ii < 8; ii++) {
        int row = row0 + ((ii < 4) ? ii : (ii + 60));  // +64 for second half
        float* crow = C + (size_t)row * N;
#pragma unroll
        for (int half = 0; half < 2; half++) {
            int col = col0 + half * 64;
            float v[4];
#pragma unroll
            for (int j = 0; j < 4; j++) v[j] = acc[ii][half * 4 + j];
            if (MODE == 0) {
                // q,k columns get elu(x)+1 = (x>0 ? x+1 : exp(x)); v columns pass through.
                // col..col+3 are on the same side of the 2048 boundary (aligned).
                if (col < 2 * EMBED) {
#pragma unroll
                    for (int j = 0; j < 4; j++)
                        v[j] = (v[j] > 0.0f) ? (v[j] + 1.0f) : expf(v[j]);
                }
            } else {
#pragma unroll
                for (int j = 0; j < 4; j++) v[j] += bias[col + j];
            }
            float4 vv = make_float4(v[0], v[1], v[2], v[3]);
            *(float4*)(crow + col) = vv;
        }
    }
}

__global__ void qkv_gemm_kernel(const float* __restrict__ x,
                                const float* __restrict__ W_qkv) {
    gemm_body<0>(x, W_qkv, g_qkv, nullptr, QKV_N, EMBED);
}

__global__ void out_gemm_kernel(const float* __restrict__ W_out,
                                const float* __restrict__ b_out,
                                float* __restrict__ out) {
    gemm_body<1>(g_y, W_out, out, b_out, EMBED, EMBED);
}

// ---------------------------------------------------------------------------
// kv[bh][dk][dv] = sum_n k[bh,n,dk] * v[bh,n,dv];  ksum[bh][d] = sum_n k[bh,n,d]
// grid (64 bh, 16 splits of N), block 256.
// Thread (r = tid/64, c = tid&63) owns dk in {r, r+4, ..., r+60}, dv = c.
// ---------------------------------------------------------------------------
__global__ void kv_reduce_kernel() {
    const int bh = blockIdx.x;           // b*16 + h
    const int b = bh >> 4, h = bh & 15;
    const int split = blockIdx.y;        // 0..15, 256 rows each
    const int tid = threadIdx.x;
    const int r = tid >> 6;              // 0..3
    const int c = tid & 63;              // 0..63

    const float* kbase = g_qkv + (size_t)(b * SEQ) * QKV_N + EMBED + h * HDIM;
    const float* vbase = kbase + EMBED;  // v is one EMBED further along columns

    __shared__ float ks[4][64];
    __shared__ float vs[4][64];

    float acc[16];
#pragma unroll
    for (int i = 0; i < 16; i++) acc[i] = 0.0f;
    float ksum_acc = 0.0f;

    const int n0 = split * 256;
    for (int n = n0; n < n0 + 256; n += 4) {
        ks[r][c] = kbase[(size_t)(n + r) * QKV_N + c];
        vs[r][c] = vbase[(size_t)(n + r) * QKV_N + c];
        __syncthreads();
#pragma unroll
        for (int rr = 0; rr < 4; rr++) {
            float vval = vs[rr][c];
#pragma unroll
            for (int i = 0; i < 16; i++)
                acc[i] += ks[rr][i * 4 + r] * vval;
        }
        if (r == 0)
            ksum_acc += ks[0][c] + ks[1][c] + ks[2][c] + ks[3][c];
        __syncthreads();
    }

    float* kv_out = g_kv + (size_t)bh * HDIM * HDIM;
#pragma unroll
    for (int i = 0; i < 16; i++)
        atomicAdd(&kv_out[(i * 4 + r) * HDIM + c], acc[i]);
    if (r == 0)
        atomicAdd(&g_ksum[bh * HDIM + c], ksum_acc);
}

// ---------------------------------------------------------------------------
// y[b,n,h*64+dv] = (sum_dk q[bh,n,dk]*kv[dk][dv]) / (sum_dk q[bh,n,dk]*ksum[dk] + 1e-6)
// grid (64 bh, 32 tiles of 128 rows), block 256 (4 rows x 64 cols per step).
// ---------------------------------------------------------------------------
__global__ void attn_apply_kernel() {
    const int bh = blockIdx.x;
    const int b = bh >> 4, h = bh & 15;
    const int tile = blockIdx.y;
    const int tid = threadIdx.x;
    const int r = tid >> 6;
    const int c = tid & 63;

    __shared__ float kvs[HDIM * HDIM];   // 16 KB
    __shared__ float ksums[HDIM];
    __shared__ float qs[4][64];

    const float* kv_in = g_kv + (size_t)bh * HDIM * HDIM;
    for (int i = tid; i < HDIM * HDIM; i += 256) kvs[i] = kv_in[i];
    if (tid < HDIM) ksums[tid] = g_ksum[bh * HDIM + tid];
    __syncthreads();

    const float* qbase = g_qkv + (size_t)(b * SEQ) * QKV_N + h * HDIM;
    float* ybase = g_y + (size_t)(b * SEQ) * EMBED + h * HDIM;

    const int n0 = tile * 128;
    for (int n = n0; n < n0 + 128; n += 4) {
        qs[r][c] = qbase[(size_t)(n + r) * QKV_N + c];
        __syncthreads();
        float num = 0.0f, den = 0.0f;
#pragma unroll
        for (int e = 0; e < HDIM; e++) {
            float qe = qs[r][e];
            num += qe * kvs[e * HDIM + c];
            den += qe * ksums[e];
        }
        ybase[(size_t)(n + r) * EMBED + c] = num / (den + 1e-6f);
        __syncthreads();
    }
}

// ---------------------------------------------------------------------------
// Launch: zero -> qkv gemm (+elu) -> kv reduce -> attn apply -> out gemm (+bias)
// ---------------------------------------------------------------------------
extern "C" void kernel_launch(void* const* d_in, const int* in_sizes, int n_in,
                              void* d_out, int out_size) {
    const float* x     = (const float*)d_in[0];
    const float* W_qkv = (const float*)d_in[1];
    const float* W_out = (const float*)d_in[2];
    const float* b_out = (const float*)d_in[3];
    float* out = (float*)d_out;

    // zero kv/ksum accumulators (262144 + 4096 floats)
    zero_acc_kernel<<<1024, 256>>>();

    // QKV = x @ W_qkv, elu+1 fused on q,k columns
    qkv_gemm_kernel<<<dim3(QKV_N / 128, MROWS / 128), 256>>>(x, W_qkv);

    // kv and ksum reductions over N
    kv_reduce_kernel<<<dim3(BATCH * HEADS, 16), 256>>>();

    // numerator / normalizer
    attn_apply_kernel<<<dim3(BATCH * HEADS, SEQ / 128), 256>>>();

    // out = y @ W_out + b_out
    out_gemm_kernel<<<dim3(EMBED / 128, MROWS / 128), 256>>>(W_out, b_out, out);
}

// round 5
// speedup vs baseline: 2.6315x; 2.6315x over previous
#include <cuda_runtime.h>
#include <cuda_bf16.h>
#include <math.h>
#include <stdint.h>

// Problem constants
#define BATCH   4
#define SEQ     4096
#define EMBED   1024
#define HEADS   16
#define HDIM    64
#define MROWS   (BATCH * SEQ)          // 16384
#define QKV_N   (3 * EMBED)            // 3072

// Scratch (static device globals)
__device__ float g_qkv[(size_t)MROWS * QKV_N];      // 192 MB
__device__ float g_y[(size_t)MROWS * EMBED];        //  64 MB (tf32-rounded at write)
__device__ float g_x_r[(size_t)MROWS * EMBED];      //  64 MB (tf32-rounded x)
__device__ float g_wq_r[(size_t)EMBED * QKV_N];     //  12 MB (tf32-rounded W_qkv)
__device__ float g_wo_r[(size_t)EMBED * EMBED];     //   4 MB (tf32-rounded W_out)
__device__ float g_kv[BATCH * HEADS * HDIM * HDIM];
__device__ float g_ksum[BATCH * HEADS * HDIM];

// ---------------------------------------------------------------------------
// helpers
// ---------------------------------------------------------------------------
__device__ __forceinline__ float round_tf32(float f) {
    uint32_t o;
    asm("cvt.rna.tf32.f32 %0, %1;" : "=r"(o) : "f"(f));
    return __uint_as_float(o);
}

__device__ __forceinline__ void mma_16n8k8_tf32(float c[4], const uint32_t a[4],
                                                const uint32_t b[2]) {
    asm volatile(
        "mma.sync.aligned.m16n8k8.row.col.f32.tf32.tf32.f32 "
        "{%0,%1,%2,%3}, {%4,%5,%6,%7}, {%8,%9}, {%0,%1,%2,%3};"
        : "+f"(c[0]), "+f"(c[1]), "+f"(c[2]), "+f"(c[3])
        : "r"(a[0]), "r"(a[1]), "r"(a[2]), "r"(a[3]), "r"(b[0]), "r"(b[1]));
}

// ---------------------------------------------------------------------------
// tf32 pre-rounding (rna) so the in-mma truncation is exact
// ---------------------------------------------------------------------------
__global__ void round_tf32_kernel(const float* __restrict__ in,
                                  float* __restrict__ out, int n4) {
    int i = blockIdx.x * 256 + threadIdx.x;
    if (i < n4) {
        float4 v = ((const float4*)in)[i];
        v.x = round_tf32(v.x); v.y = round_tf32(v.y);
        v.z = round_tf32(v.z); v.w = round_tf32(v.w);
        ((float4*)out)[i] = v;
    }
}

// ---------------------------------------------------------------------------
// zero kv/ksum accumulators (atomics accumulate into them every replay)
// ---------------------------------------------------------------------------
__global__ void zero_acc_kernel() {
    int i = blockIdx.x * 256 + threadIdx.x;
    if (i < BATCH * HEADS * HDIM * HDIM) g_kv[i] = 0.0f;
    if (i < BATCH * HEADS * HDIM)        g_ksum[i] = 0.0f;
}

// ---------------------------------------------------------------------------
// tf32 mma.sync GEMM: C[M,N] = A[M,K] @ W[K,N]   (W row-major, no transpose)
// Block 128x128, K-step 32, 2-stage cp.async double buffer, 8 warps.
// Warp tile 64(M) x 32(N) = 4x4 m16n8k8 tiles.
// MODE 0: elu(x)+1 fused on global cols < 2048.  MODE 1: +bias fused.
// ---------------------------------------------------------------------------
#define AS_STRIDE 36    // floats per A row (32 + 4 pad): bank = (4*g+t), conflict-free
#define BS_STRIDE 136   // floats per B row (128 + 8 pad): bank = (8*t+g), conflict-free
#define A_STAGE_B (128 * AS_STRIDE * 4)            // 18432
#define B_STAGE_B (32 * BS_STRIDE * 4)             // 17408
#define STAGE_B   (A_STAGE_B + B_STAGE_B)          // 35840
#define GEMM_SMEM (2 * STAGE_B)                    // 71680

template <int MODE>
__global__ void __launch_bounds__(256, 2) gemm_mma_kernel(
    const float* __restrict__ A,    // [M, K] (tf32-rounded)
    const float* __restrict__ W,    // [K, N] (tf32-rounded)
    float* __restrict__ C,          // [M, Ncols]
    const float* __restrict__ bias, // MODE 1
    int Ncols, int K)
{
    extern __shared__ __align__(16) float smem[];
    const int tid = threadIdx.x;
    const int wid = tid >> 5, lane = tid & 31;
    const int group = lane >> 2, tig = lane & 3;
    const int warp_m = wid & 1;          // 0..1 -> 64-row halves
    const int warp_n = wid >> 1;         // 0..3 -> 32-col quarters
    const int row0 = blockIdx.y * 128;
    const int col0 = blockIdx.x * 128;
    const int m_off = warp_m * 64;
    const int n_off = warp_n * 32;

    // ---- async loaders ----
    auto load_stage = [&](int stage, int kb) {
        float* As = smem + stage * (STAGE_B / 4);
        float* Bs = As + (A_STAGE_B / 4);
        const int k0 = kb * 32;
#pragma unroll
        for (int i = 0; i < 4; i++) {          // A: 1024 float4s
            int idx = i * 256 + tid;
            int r = idx >> 3, c4 = idx & 7;
            const float* gp = A + (size_t)(row0 + r) * K + k0 + c4 * 4;
            uint32_t sa = __cvta_generic_to_shared(As + r * AS_STRIDE + c4 * 4);
            asm volatile("cp.async.cg.shared.global [%0], [%1], 16;"
                         :: "r"(sa), "l"(gp) : "memory");
        }
#pragma unroll
        for (int i = 0; i < 4; i++) {          // B: 1024 float4s
            int idx = i * 256 + tid;
            int kr = idx >> 5, c4 = idx & 31;
            const float* gp = W + (size_t)(k0 + kr) * Ncols + col0 + c4 * 4;
            uint32_t sa = __cvta_generic_to_shared(Bs + kr * BS_STRIDE + c4 * 4);
            asm volatile("cp.async.cg.shared.global [%0], [%1], 16;"
                         :: "r"(sa), "l"(gp) : "memory");
        }
    };

    float c[4][4][4];
#pragma unroll
    for (int mt = 0; mt < 4; mt++)
#pragma unroll
        for (int nt = 0; nt < 4; nt++)
#pragma unroll
            for (int e = 0; e < 4; e++) c[mt][nt][e] = 0.0f;

    const int nkb = K / 32;
    load_stage(0, 0);
    asm volatile("cp.async.commit_group;" ::: "memory");

    for (int kb = 0; kb < nkb; kb++) {
        if (kb + 1 < nkb) {
            load_stage((kb + 1) & 1, kb + 1);
            asm volatile("cp.async.commit_group;" ::: "memory");
            asm volatile("cp.async.wait_group 1;" ::: "memory");
        } else {
            asm volatile("cp.async.wait_group 0;" ::: "memory");
        }
        __syncthreads();

        const float* As = smem + (kb & 1) * (STAGE_B / 4);
        const float* Bs = As + (A_STAGE_B / 4);

#pragma unroll
        for (int j = 0; j < 4; j++) {          // 4 x k8 within K32
            const int k8 = j * 8;
            uint32_t af[4][4], bf[4][2];
#pragma unroll
            for (int mt = 0; mt < 4; mt++) {
                int r = m_off + mt * 16 + group;
                af[mt][0] = __float_as_uint(As[(r)     * AS_STRIDE + k8 + tig]);
                af[mt][1] = __float_as_uint(As[(r + 8) * AS_STRIDE + k8 + tig]);
                af[mt][2] = __float_as_uint(As[(r)     * AS_STRIDE + k8 + tig + 4]);
                af[mt][3] = __float_as_uint(As[(r + 8) * AS_STRIDE + k8 + tig + 4]);
            }
#pragma unroll
            for (int nt = 0; nt < 4; nt++) {
                int n = n_off + nt * 8 + group;
                bf[nt][0] = __float_as_uint(Bs[(k8 + tig)     * BS_STRIDE + n]);
                bf[nt][1] = __float_as_uint(Bs[(k8 + tig + 4) * BS_STRIDE + n]);
            }
#pragma unroll
            for (int mt = 0; mt < 4; mt++)
#pragma unroll
                for (int nt = 0; nt < 4; nt++)
                    mma_16n8k8_tf32(c[mt][nt], af[mt], bf[nt]);
        }
        __syncthreads();
    }

    // ---- epilogue: fused op + direct global stores (float2 per row-pair) ----
#pragma unroll
    for (int mt = 0; mt < 4; mt++) {
        int r0 = row0 + m_off + mt * 16 + group;
        int r1 = r0 + 8;
#pragma unroll
        for (int nt = 0; nt < 4; nt++) {
            int col = col0 + n_off + nt * 8 + 2 * tig;
            float v0 = c[mt][nt][0], v1 = c[mt][nt][1];
            float v2 = c[mt][nt][2], v3 = c[mt][nt][3];
            if (MODE == 0) {
                if (col < 2 * EMBED) {  // q,k columns: elu(x)+1
                    v0 = (v0 > 0.0f) ? (v0 + 1.0f) : expf(v0);
                    v1 = (v1 > 0.0f) ? (v1 + 1.0f) : expf(v1);
                    v2 = (v2 > 0.0f) ? (v2 + 1.0f) : expf(v2);
                    v3 = (v3 > 0.0f) ? (v3 + 1.0f) : expf(v3);
                }
            } else {
                float b0 = bias[col], b1 = bias[col + 1];
                v0 += b0; v1 += b1; v2 += b0; v3 += b1;
            }
            *(float2*)(C + (size_t)r0 * Ncols + col) = make_float2(v0, v1);
            *(float2*)(C + (size_t)r1 * Ncols + col) = make_float2(v2, v3);
        }
    }
}

// ---------------------------------------------------------------------------
// kv[bh][dk][dv] = sum_n k * v;  ksum[bh][d] = sum_n k
// ---------------------------------------------------------------------------
__global__ void kv_reduce_kernel() {
    const int bh = blockIdx.x;
    const int b = bh >> 4, h = bh & 15;
    const int split = blockIdx.y;
    const int tid = threadIdx.x;
    const int r = tid >> 6;
    const int c = tid & 63;

    const float* kbase = g_qkv + (size_t)(b * SEQ) * QKV_N + EMBED + h * HDIM;
    const float* vbase = kbase + EMBED;

    __shared__ float ks[4][64];
    __shared__ float vs[4][64];

    float acc[16];
#pragma unroll
    for (int i = 0; i < 16; i++) acc[i] = 0.0f;
    float ksum_acc = 0.0f;

    const int n0 = split * 256;
    for (int n = n0; n < n0 + 256; n += 4) {
        ks[r][c] = kbase[(size_t)(n + r) * QKV_N + c];
        vs[r][c] = vbase[(size_t)(n + r) * QKV_N + c];
        __syncthreads();
#pragma unroll
        for (int rr = 0; rr < 4; rr++) {
            float vval = vs[rr][c];
#pragma unroll
            for (int i = 0; i < 16; i++)
                acc[i] += ks[rr][i * 4 + r] * vval;
        }
        if (r == 0)
            ksum_acc += ks[0][c] + ks[1][c] + ks[2][c] + ks[3][c];
        __syncthreads();
    }

    float* kv_out = g_kv + (size_t)bh * HDIM * HDIM;
#pragma unroll
    for (int i = 0; i < 16; i++)
        atomicAdd(&kv_out[(i * 4 + r) * HDIM + c], acc[i]);
    if (r == 0)
        atomicAdd(&g_ksum[bh * HDIM + c], ksum_acc);
}

// ---------------------------------------------------------------------------
// y = (q @ kv) / (q . ksum + 1e-6); y rounded to tf32 for the out GEMM
// ---------------------------------------------------------------------------
__global__ void attn_apply_kernel() {
    const int bh = blockIdx.x;
    const int b = bh >> 4, h = bh & 15;
    const int tile = blockIdx.y;
    const int tid = threadIdx.x;
    const int r = tid >> 6;
    const int c = tid & 63;

    __shared__ float kvs[HDIM * HDIM];
    __shared__ float ksums[HDIM];
    __shared__ float qs[4][64];

    const float* kv_in = g_kv + (size_t)bh * HDIM * HDIM;
    for (int i = tid; i < HDIM * HDIM; i += 256) kvs[i] = kv_in[i];
    if (tid < HDIM) ksums[tid] = g_ksum[bh * HDIM + tid];
    __syncthreads();

    const float* qbase = g_qkv + (size_t)(b * SEQ) * QKV_N + h * HDIM;
    float* ybase = g_y + (size_t)(b * SEQ) * EMBED + h * HDIM;

    const int n0 = tile * 128;
    for (int n = n0; n < n0 + 128; n += 4) {
        qs[r][c] = qbase[(size_t)(n + r) * QKV_N + c];
        __syncthreads();
        float num = 0.0f, den = 0.0f;
#pragma unroll
        for (int e = 0; e < HDIM; e++) {
            float qe = qs[r][e];
            num += qe * kvs[e * HDIM + c];
            den += qe * ksums[e];
        }
        ybase[(size_t)(n + r) * EMBED + c] = round_tf32(num / (den + 1e-6f));
        __syncthreads();
    }
}

// ---------------------------------------------------------------------------
// Launch: round inputs -> zero -> qkv gemm(tf32 mma + elu) -> kv reduce ->
//         attn apply -> out gemm(tf32 mma + bias)
// ---------------------------------------------------------------------------
extern "C" void kernel_launch(void* const* d_in, const int* in_sizes, int n_in,
                              void* d_out, int out_size) {
    const float* x     = (const float*)d_in[0];
    const float* W_qkv = (const float*)d_in[1];
    const float* W_out = (const float*)d_in[2];
    const float* b_out = (const float*)d_in[3];
    float* out = (float*)d_out;

    cudaFuncSetAttribute(gemm_mma_kernel<0>, cudaFuncAttributeMaxDynamicSharedMemorySize, GEMM_SMEM);
    cudaFuncSetAttribute(gemm_mma_kernel<1>, cudaFuncAttributeMaxDynamicSharedMemorySize, GEMM_SMEM);

    float *x_r, *wq_r, *wo_r, *qkv_ptr, *y_ptr;
    cudaGetSymbolAddress((void**)&x_r, g_x_r);
    cudaGetSymbolAddress((void**)&wq_r, g_wq_r);
    cudaGetSymbolAddress((void**)&wo_r, g_wo_r);
    cudaGetSymbolAddress((void**)&qkv_ptr, g_qkv);
    cudaGetSymbolAddress((void**)&y_ptr, g_y);

    // tf32-round inputs (rna)
    round_tf32_kernel<<<(MROWS * EMBED / 4 + 255) / 256, 256>>>(x, x_r, MROWS * EMBED / 4);
    round_tf32_kernel<<<(EMBED * QKV_N / 4 + 255) / 256, 256>>>(W_qkv, wq_r, EMBED * QKV_N / 4);
    round_tf32_kernel<<<(EMBED * EMBED / 4 + 255) / 256, 256>>>(W_out, wo_r, EMBED * EMBED / 4);

    zero_acc_kernel<<<1024, 256>>>();

    // QKV = x @ W_qkv (tf32 mma.sync), elu+1 fused on q,k columns
    gemm_mma_kernel<0><<<dim3(QKV_N / 128, MROWS / 128), 256, GEMM_SMEM>>>(
        x_r, wq_r, qkv_ptr, nullptr, QKV_N, EMBED);

    kv_reduce_kernel<<<dim3(BATCH * HEADS, 16), 256>>>();

    attn_apply_kernel<<<dim3(BATCH * HEADS, SEQ / 128), 256>>>();

    // out = y @ W_out + b_out (tf32 mma.sync)
    gemm_mma_kernel<1><<<dim3(EMBED / 128, MROWS / 128), 256, GEMM_SMEM>>>(
        y_ptr, wo_r, out, b_out, EMBED, EMBED);
}